// round 8
// baseline (speedup 1.0000x reference)
#include <cuda_runtime.h>
#include <math.h>

// Problem shapes (fixed by the dataset)
#define N_Q 256      // queries
#define DIM 512      // feature dim
#define QB  2048     // bank size
#define NC  1000     // classes
#define IMG 150528   // 3*224*224
#define IMG4 (IMG/4) // 37632 float4 per image
#define KNN 4

// Output layout (float32, concatenated in reference return order)
#define OFF_LBL 0
#define OFF_PRB 256
#define OFF_IMG 256256           // 256 + 256*1000
#define OFF_GRD 38791424         // OFF_IMG + 256*150528

#define BM 64
#define BN 64
#define BK 32
#define NT (DIM / BK)            // 16 k-tiles
#define NBX (QB / BN)            // 32 partial top-4 blocks per query

// Dynamic smem layout for dist_topk:
//   As2: float2[2][BK][BMps]  (dup pairs (a,a))
//   Bp0: float [2][BK][32]    (col pairs 4t,4t+1, k-rotated slots)
//   Bp1: float [2][BK][32]    (col pairs 4t+2,4t+3)
#define BMps 66
#define SM_BROW 32
#define SM_A_F2   (2 * BK * BMps)     // float2 elements
#define SM_B_F    (2 * BK * SM_BROW)  // floats per array
#define SMEM_BYTES (SM_A_F2 * 8 + 2 * SM_B_F * 4)   // 33792 + 16384 = 50176

// Scratch (static device globals — no allocations allowed)
__device__ float g_qinv[N_Q];
__device__ float g_binv[QB];
__device__ float g_pv[N_Q * NBX * 4];   // partial top-4 values per (q, col-block)
__device__ int   g_pi[N_Q * NBX * 4];   // partial top-4 indices
__device__ int   g_idx[N_Q * KNN];

typedef unsigned long long u64;

// packed fp32x2 FMA (sm_100+): one issue slot, two fp32 FMAs, .rn (bit-exact
// vs scalar fmaf; validated rel_err 0.0 in an earlier round)
__device__ __forceinline__ void fma2(u64& d, u64 a, u64 b) {
    asm("fma.rn.f32x2 %0, %1, %2, %0;" : "+l"(d) : "l"(a), "l"(b));
}
__device__ __forceinline__ void unpk(u64 v, float& lo, float& hi) {
    asm("mov.b64 {%0, %1}, %2;" : "=f"(lo), "=f"(hi) : "l"(v));
}

// ---------------------------------------------------------------------------
// top-4 helpers: largest-first, ties -> smaller index (lax.top_k order)
// ---------------------------------------------------------------------------
__device__ __forceinline__ bool d_better(float v, int j, float v2, int j2) {
    return (v > v2) || (v == v2 && j < j2);
}
__device__ __forceinline__ void d_insert(float v, int j, float* bv, int* bi) {
    if (!d_better(v, j, bv[3], bi[3])) return;
    int p = 3;
    while (p > 0 && d_better(v, j, bv[p - 1], bi[p - 1])) {
        bv[p] = bv[p - 1]; bi[p] = bi[p - 1]; p--;
    }
    bv[p] = v; bi[p] = j;
}
template<int SPAN>
__device__ __forceinline__ void shfl_merge_top4(float* bv, int* bi) {
#pragma unroll
    for (int o = SPAN / 2; o; o >>= 1) {
        float pv[4]; int pi[4];
#pragma unroll
        for (int k = 0; k < 4; k++) {
            pv[k] = __shfl_xor_sync(0xffffffffu, bv[k], o);
            pi[k] = __shfl_xor_sync(0xffffffffu, bi[k], o);
        }
#pragma unroll
        for (int k = 0; k < 4; k++) d_insert(pv[k], pi[k], bv, bi);
    }
}

// ---------------------------------------------------------------------------
// K0: inverse L2 norms for query rows and bank rows (ONE WARP per row)
// ---------------------------------------------------------------------------
__global__ void norms_kernel(const float* __restrict__ feat,
                             const float* __restrict__ bank) {
    int w    = (blockIdx.x * blockDim.x + threadIdx.x) >> 5;
    int lane = threadIdx.x & 31;
    if (w >= N_Q + QB) return;
    const float* row = (w < N_Q) ? feat + (size_t)w * DIM
                                 : bank + (size_t)(w - N_Q) * DIM;
    const float4* r4 = (const float4*)row;
    float s = 0.f;
#pragma unroll
    for (int i = 0; i < 4; i++) {
        float4 v = r4[lane + 32 * i];
        s += v.x * v.x + v.y * v.y + v.z * v.z + v.w * v.w;
    }
#pragma unroll
    for (int o = 16; o; o >>= 1) s += __shfl_xor_sync(0xffffffffu, s, o);
    if (lane == 0) {
        float inv = 1.0f / fmaxf(sqrtf(s), 1e-12f);
        if (w < N_Q) g_qinv[w] = inv;
        else         g_binv[w - N_Q] = inv;
    }
}

// ---------------------------------------------------------------------------
// K1: distance GEMM + fused per-tile top-4 partials.
// 64x64x32 tile, 512 threads, micro-tile 2x4 via FFMA2 (packed fp32x2).
// Crossbar-optimized: per warp-k = 1 LDS.128 (A dup-pairs, broadcast, 1 phase)
//                               + 2 LDS.64  (B pair arrays, 128B rows, 1 phase each)
//                               + 4 FFMA2.
// Double-buffered smem: LDG(t+1) -> compute(t) -> STS(t+1) -> bar.
// grid = (QB/64, N_Q/64) = (32, 4) = 128 CTAs.
// ---------------------------------------------------------------------------
__global__ void __launch_bounds__(512)
dist_topk_kernel(const float* __restrict__ A,   // features (N_Q,DIM)
                 const float* __restrict__ B) { // bank     (QB,DIM)
    extern __shared__ char smraw[];
    float2* As2 = (float2*)smraw;                    // [2][BK][BMps]
    float*  Bp0 = (float*)(smraw + SM_A_F2 * 8);     // [2][BK][32]
    float*  Bp1 = Bp0 + SM_B_F;                      // [2][BK][32]

    int tid = threadIdx.x;
    int tx = tid & 15;           // 0..15 -> cols 4tx..4tx+3
    int ty = tid >> 4;           // 0..31 -> rows 2ty, 2ty+1
    int qb = blockIdx.y * BM;
    int bb = blockIdx.x * BN;
    int r  = tid >> 3;           // 0..63 (load row within tile)
    int c4 = tid & 7;            // 0..7  (load float4-col within tile)

    const float4* Ag = (const float4*)(A + (size_t)(qb + r) * DIM) + c4;
    const float4* Bg = (const float4*)(B + (size_t)(bb + r) * DIM) + c4;

    u64 acc00 = 0, acc01 = 0, acc10 = 0, acc11 = 0;

    // B store addressing: col r -> array (r&2), pair slot ((r>>2)+kk)&15, elem r&1
    float* barr = (r & 2) ? Bp1 : Bp0;
    int bslot0 = r >> 2;
    int belem  = r & 1;

    float4 va = Ag[0];
    float4 vb = Bg[0];
    // store tile 0 into buffer 0
    {
        float vax[4] = {va.x, va.y, va.z, va.w};
        float vbx[4] = {vb.x, vb.y, vb.z, vb.w};
#pragma unroll
        for (int u = 0; u < 4; u++) {
            int kk = c4 * 4 + u;
            As2[kk * BMps + r] = make_float2(vax[u], vax[u]);
            barr[kk * SM_BROW + (((bslot0 + kk) & 15) << 1) + belem] = vbx[u];
        }
    }
    __syncthreads();

    for (int t = 0; t < NT; t++) {
        if (t + 1 < NT) {                       // prefetch next tile (LDG early)
            va = Ag[(t + 1) * (BK / 4)];
            vb = Bg[(t + 1) * (BK / 4)];
        }
        {   // compute on buffer t&1
            const float2* as = As2 + (t & 1) * (BK * BMps);
            const float*  b0 = Bp0 + (t & 1) * (BK * SM_BROW);
            const float*  b1 = Bp1 + (t & 1) * (BK * SM_BROW);
#pragma unroll
            for (int k = 0; k < BK; k++) {
                ulonglong2 av = *(const ulonglong2*)(as + k * BMps + ty * 2);
                u64 b01 = *(const u64*)(b0 + k * SM_BROW + (((tx + k) & 15) << 1));
                u64 b23 = *(const u64*)(b1 + k * SM_BROW + (((tx + k) & 15) << 1));
                fma2(acc00, av.x, b01); fma2(acc01, av.x, b23);
                fma2(acc10, av.y, b01); fma2(acc11, av.y, b23);
            }
        }
        if (t + 1 < NT) {                       // store prefetched tile -> other buffer
            int nb = (t + 1) & 1;
            float2* as = As2 + nb * (BK * BMps);
            float*  ba = barr + nb * (BK * SM_BROW);
            float vax[4] = {va.x, va.y, va.z, va.w};
            float vbx[4] = {vb.x, vb.y, vb.z, vb.w};
#pragma unroll
            for (int u = 0; u < 4; u++) {
                int kk = c4 * 4 + u;
                as[kk * BMps + r] = make_float2(vax[u], vax[u]);
                ba[kk * SM_BROW + (((bslot0 + kk) & 15) << 1) + belem] = vbx[u];
            }
        }
        __syncthreads();
    }

    // Epilogue: distances + per-row top-4 over this CTA's 64 columns.
    float bj[4];
#pragma unroll
    for (int j = 0; j < 4; j++) bj[j] = g_binv[bb + tx * 4 + j];

    u64 accs[2][2] = {{acc00, acc01}, {acc10, acc11}};
#pragma unroll
    for (int i = 0; i < 2; i++) {
        int q = qb + ty * 2 + i;
        float qi = g_qinv[q];
        float d0, d1, d2, d3;
        unpk(accs[i][0], d0, d1);
        unpk(accs[i][1], d2, d3);
        float bv[4] = {-3.0e38f, -3.0e38f, -3.0e38f, -3.0e38f};
        int   bi[4] = {0x7fffffff, 0x7fffffff, 0x7fffffff, 0x7fffffff};
        int b0 = bb + tx * 4;
        d_insert(1.0f - d0 * qi * bj[0], b0 + 0, bv, bi);
        d_insert(1.0f - d1 * qi * bj[1], b0 + 1, bv, bi);
        d_insert(1.0f - d2 * qi * bj[2], b0 + 2, bv, bi);
        d_insert(1.0f - d3 * qi * bj[3], b0 + 3, bv, bi);
        shfl_merge_top4<16>(bv, bi);   // across the 16 tx lanes sharing this row
        if (tx == 0) {
            int base = (q * NBX + blockIdx.x) * 4;
#pragma unroll
            for (int k = 0; k < 4; k++) { g_pv[base + k] = bv[k]; g_pi[base + k] = bi[k]; }
        }
    }
}

// ---------------------------------------------------------------------------
// K2: final top-4 merge. One warp per query folds 32 partials x 4 = 128
// candidates. 32 blocks x 256 threads (8 warps each).
// ---------------------------------------------------------------------------
__global__ void merge_topk_kernel() {
    int tid  = threadIdx.x;
    int lane = tid & 31, wid = tid >> 5;
    int q = blockIdx.x * 8 + wid;

    const float4* pv4 = (const float4*)(g_pv + q * NBX * 4);
    const int4*   pi4 = (const int4*)  (g_pi + q * NBX * 4);
    float4 v = pv4[lane];   // 128 candidates = 1 float4 per lane
    int4   j = pi4[lane];

    float bv[4] = {-3.0e38f, -3.0e38f, -3.0e38f, -3.0e38f};
    int   bi[4] = {0x7fffffff, 0x7fffffff, 0x7fffffff, 0x7fffffff};
    d_insert(v.x, j.x, bv, bi);
    d_insert(v.y, j.y, bv, bi);
    d_insert(v.z, j.z, bv, bi);
    d_insert(v.w, j.w, bv, bi);
    shfl_merge_top4<32>(bv, bi);
    if (lane < 4) g_idx[q * 4 + lane] = bi[lane];
}

// ---------------------------------------------------------------------------
// K3: fused gather. grid=(256, 22), 256 threads.
//   blockIdx.y < 21 : pred_images chunk (HBM-bound bulk, 82.9% of spec)
//   blockIdx.y ==21 : grads_m + pred_probs + pred_labels (hidden in the wave)
// ---------------------------------------------------------------------------
__global__ void gather_kernel(const float* __restrict__ img,
                              const float* __restrict__ bank,
                              const float* __restrict__ probs,
                              float* __restrict__ out) {
    int q = blockIdx.x;
    int tid = threadIdx.x;
    __shared__ int ix[4];
    if (tid < 4) ix[tid] = g_idx[q * 4 + tid];
    __syncthreads();

    if (blockIdx.y < 21) {
        const float4* im = (const float4*)img;
        float4* o = (float4*)(out + OFF_IMG) + (size_t)q * IMG4;
        size_t r0 = (size_t)ix[0] * IMG4;
        size_t r1 = (size_t)ix[1] * IMG4;
        size_t r2 = (size_t)ix[2] * IMG4;
        size_t r3 = (size_t)ix[3] * IMG4;
#pragma unroll
        for (int t = 0; t < 7; t++) {
            int f = blockIdx.y * 1792 + t * 256 + tid;   // 21*1792 = 37632 = IMG4
            float4 a = im[r0 + f];
            float4 b = im[r1 + f];
            float4 c = im[r2 + f];
            float4 d = im[r3 + f];
            float4 r;
            r.x = 0.25f * (a.x + b.x + c.x + d.x);
            r.y = 0.25f * (a.y + b.y + c.y + d.y);
            r.z = 0.25f * (a.z + b.z + c.z + d.z);
            r.w = 0.25f * (a.w + b.w + c.w + d.w);
            __stcs(&o[f], r);   // streaming store: no reuse of output
        }
        return;
    }

    // ---- small outputs slice ----
    if (tid < 128) {
        const float4* b0 = (const float4*)(bank + (size_t)ix[0] * DIM);
        const float4* b1 = (const float4*)(bank + (size_t)ix[1] * DIM);
        const float4* b2 = (const float4*)(bank + (size_t)ix[2] * DIM);
        const float4* b3 = (const float4*)(bank + (size_t)ix[3] * DIM);
        float4 a = b0[tid], b = b1[tid], c = b2[tid], d = b3[tid];
        float4 r;
        r.x = 0.25f * (a.x + b.x + c.x + d.x);
        r.y = 0.25f * (a.y + b.y + c.y + d.y);
        r.z = 0.25f * (a.z + b.z + c.z + d.z);
        r.w = 0.25f * (a.w + b.w + c.w + d.w);
        ((float4*)(out + OFF_GRD + (size_t)q * DIM))[tid] = r;
    }

    float bestv = -3.0e38f;
    int   bestc = 0x7fffffff;
    if (tid < 250) {
        const float4* p0 = (const float4*)(probs + (size_t)ix[0] * NC);
        const float4* p1 = (const float4*)(probs + (size_t)ix[1] * NC);
        const float4* p2 = (const float4*)(probs + (size_t)ix[2] * NC);
        const float4* p3 = (const float4*)(probs + (size_t)ix[3] * NC);
        float4 a = p0[tid], b = p1[tid], c = p2[tid], d = p3[tid];
        float4 m;
        m.x = 0.25f * (a.x + b.x + c.x + d.x);
        m.y = 0.25f * (a.y + b.y + c.y + d.y);
        m.z = 0.25f * (a.z + b.z + c.z + d.z);
        m.w = 0.25f * (a.w + b.w + c.w + d.w);
        ((float4*)(out + OFF_PRB + (size_t)q * NC))[tid] = m;
        int c0 = tid * 4;
        bestv = m.x; bestc = c0;
        if (m.y > bestv) { bestv = m.y; bestc = c0 + 1; }
        if (m.z > bestv) { bestv = m.z; bestc = c0 + 2; }
        if (m.w > bestv) { bestv = m.w; bestc = c0 + 3; }
    }
    __shared__ float rv[256];
    __shared__ int   rc[256];
    rv[tid] = bestv; rc[tid] = bestc;
    __syncthreads();
    for (int s = 128; s; s >>= 1) {
        if (tid < s) {
            float v2 = rv[tid + s]; int c2 = rc[tid + s];
            if (v2 > rv[tid] || (v2 == rv[tid] && c2 < rc[tid])) {
                rv[tid] = v2; rc[tid] = c2;
            }
        }
        __syncthreads();
    }
    if (tid == 0) out[OFF_LBL + q] = (float)rc[0];
}

// ---------------------------------------------------------------------------
extern "C" void kernel_launch(void* const* d_in, const int* in_sizes, int n_in,
                              void* d_out, int out_size) {
    const float* feat  = (const float*)d_in[0];
    const float* bank  = (const float*)d_in[1];
    const float* probs = (const float*)d_in[2];
    const float* img   = (const float*)d_in[3];
    float* out = (float*)d_out;

    // sticky function attribute (idempotent; needed for 50176B dynamic smem)
    cudaFuncSetAttribute(dist_topk_kernel,
                         cudaFuncAttributeMaxDynamicSharedMemorySize, SMEM_BYTES);

    norms_kernel<<<((N_Q + QB) * 32 + 255) / 256, 256>>>(feat, bank);
    dist_topk_kernel<<<dim3(QB / BN, N_Q / BM), 512, SMEM_BYTES>>>(feat, bank);
    merge_topk_kernel<<<N_Q / 8, 256>>>();
    gather_kernel<<<dim3(N_Q, 22), 256>>>(img, bank, probs, out);
}

// round 9
// speedup vs baseline: 1.0080x; 1.0080x over previous
#include <cuda_runtime.h>
#include <math.h>

// Problem shapes (fixed by the dataset)
#define N_Q 256      // queries
#define DIM 512      // feature dim
#define QB  2048     // bank size
#define NC  1000     // classes
#define IMG 150528   // 3*224*224
#define IMG4 (IMG/4) // 37632 float4 per image
#define KNN 4

// Output layout (float32, concatenated in reference return order)
#define OFF_LBL 0
#define OFF_PRB 256
#define OFF_IMG 256256           // 256 + 256*1000
#define OFF_GRD 38791424         // OFF_IMG + 256*150528

#define BM 64
#define BN 64
#define BK 32
#define SPLITK 4
#define KSPAN (DIM / SPLITK)     // 128 k's per split CTA
#define NQT (N_Q / BM)           // 4 query tiles
#define NBX (QB / BN)            // 32 bank tiles (partial top-4 blocks/query)

// Scratch (static device globals — no allocations allowed)
__device__ float g_qinv[N_Q];
__device__ float g_binv[QB];
__device__ float g_part[SPLITK * NQT * NBX * BM * BN];  // 8 MB partial dots
__device__ float g_pv[N_Q * NBX * 4];   // partial top-4 values per (q, col-block)
__device__ int   g_pi[N_Q * NBX * 4];   // partial top-4 indices
__device__ int   g_idx[N_Q * KNN];

// ---------------------------------------------------------------------------
// top-4 helpers: largest-first, ties -> smaller index (lax.top_k order)
// ---------------------------------------------------------------------------
__device__ __forceinline__ bool d_better(float v, int j, float v2, int j2) {
    return (v > v2) || (v == v2 && j < j2);
}
__device__ __forceinline__ void d_insert(float v, int j, float* bv, int* bi) {
    if (!d_better(v, j, bv[3], bi[3])) return;
    int p = 3;
    while (p > 0 && d_better(v, j, bv[p - 1], bi[p - 1])) {
        bv[p] = bv[p - 1]; bi[p] = bi[p - 1]; p--;
    }
    bv[p] = v; bi[p] = j;
}
template<int SPAN>
__device__ __forceinline__ void shfl_merge_top4(float* bv, int* bi) {
#pragma unroll
    for (int o = SPAN / 2; o; o >>= 1) {
        float pv[4]; int pi[4];
#pragma unroll
        for (int k = 0; k < 4; k++) {
            pv[k] = __shfl_xor_sync(0xffffffffu, bv[k], o);
            pi[k] = __shfl_xor_sync(0xffffffffu, bi[k], o);
        }
#pragma unroll
        for (int k = 0; k < 4; k++) d_insert(pv[k], pi[k], bv, bi);
    }
}

// ---------------------------------------------------------------------------
// K0: inverse L2 norms for query rows and bank rows (ONE WARP per row)
// ---------------------------------------------------------------------------
__global__ void norms_kernel(const float* __restrict__ feat,
                             const float* __restrict__ bank) {
    int w    = (blockIdx.x * blockDim.x + threadIdx.x) >> 5;
    int lane = threadIdx.x & 31;
    if (w >= N_Q + QB) return;
    const float* row = (w < N_Q) ? feat + (size_t)w * DIM
                                 : bank + (size_t)(w - N_Q) * DIM;
    const float4* r4 = (const float4*)row;
    float s = 0.f;
#pragma unroll
    for (int i = 0; i < 4; i++) {
        float4 v = r4[lane + 32 * i];
        s += v.x * v.x + v.y * v.y + v.z * v.z + v.w * v.w;
    }
#pragma unroll
    for (int o = 16; o; o >>= 1) s += __shfl_xor_sync(0xffffffffu, s, o);
    if (lane == 0) {
        float inv = 1.0f / fmaxf(sqrtf(s), 1e-12f);
        if (w < N_Q) g_qinv[w] = inv;
        else         g_binv[w - N_Q] = inv;
    }
}

// ---------------------------------------------------------------------------
// K1: split-K partial GEMM. R4's proven 64x64x32 core, 256 threads, 4x4
// micro-tile — but each CTA covers only 128 k's. grid (32, 4, 4) = 512 CTAs
// (~3.5 per SM) so barrier/LDS stalls of one CTA overlap another's FMAs.
// Writes 64x64 fp32 partials (L2-resident, 8 MB total).
// ---------------------------------------------------------------------------
__global__ void __launch_bounds__(256)
dist_part_kernel(const float* __restrict__ A,   // features (N_Q,DIM)
                 const float* __restrict__ B) { // bank     (QB,DIM)
    __shared__ float As[BK][BM];
    __shared__ float Bs[BK][BN];
    int tid = threadIdx.x;
    int tx = tid & 15;
    int ty = tid >> 4;
    int qb = blockIdx.y * BM;
    int bb = blockIdx.x * BN;
    int kb = blockIdx.z * KSPAN;

    float acc[4][4] = {};

    for (int k0 = kb; k0 < kb + KSPAN; k0 += BK) {
#pragma unroll
        for (int l = 0; l < 2; l++) {
            int i  = tid + l * 256;
            int r  = i >> 3;
            int c4 = i & 7;
            float4 v = *(const float4*)(A + (size_t)(qb + r) * DIM + k0 + c4 * 4);
            As[c4 * 4 + 0][r] = v.x; As[c4 * 4 + 1][r] = v.y;
            As[c4 * 4 + 2][r] = v.z; As[c4 * 4 + 3][r] = v.w;
            float4 w = *(const float4*)(B + (size_t)(bb + r) * DIM + k0 + c4 * 4);
            Bs[c4 * 4 + 0][r] = w.x; Bs[c4 * 4 + 1][r] = w.y;
            Bs[c4 * 4 + 2][r] = w.z; Bs[c4 * 4 + 3][r] = w.w;
        }
        __syncthreads();
#pragma unroll
        for (int k = 0; k < BK; k++) {
            float ra[4], rb[4];
#pragma unroll
            for (int i = 0; i < 4; i++) ra[i] = As[k][ty * 4 + i];
#pragma unroll
            for (int j = 0; j < 4; j++) rb[j] = Bs[k][tx * 4 + j];
#pragma unroll
            for (int i = 0; i < 4; i++)
#pragma unroll
                for (int j = 0; j < 4; j++)
                    acc[i][j] = fmaf(ra[i], rb[j], acc[i][j]);
        }
        __syncthreads();
    }

    // write 64x64 partial tile (coalesced float4 rows)
    float* pt = g_part +
        ((size_t)(blockIdx.z * NQT + blockIdx.y) * NBX + blockIdx.x) * (BM * BN);
#pragma unroll
    for (int i = 0; i < 4; i++) {
        int row = ty * 4 + i;
        float4 st = make_float4(acc[i][0], acc[i][1], acc[i][2], acc[i][3]);
        *(float4*)(pt + row * BN + tx * 4) = st;
    }
}

// ---------------------------------------------------------------------------
// K2: reduce splits (fixed order -> deterministic) + distance + fused
// per-tile top-4 (R4-proven epilogue). grid (32, 4), 256 threads.
// ---------------------------------------------------------------------------
__global__ void __launch_bounds__(256)
reduce_topk_kernel() {
    int tid = threadIdx.x;
    int tx = tid & 15;
    int ty = tid >> 4;
    int qb = blockIdx.y * BM;
    int bb = blockIdx.x * BN;

    const float* p0 = g_part + ((size_t)(0 * NQT + blockIdx.y) * NBX + blockIdx.x) * (BM * BN);
    const float* p1 = g_part + ((size_t)(1 * NQT + blockIdx.y) * NBX + blockIdx.x) * (BM * BN);
    const float* p2 = g_part + ((size_t)(2 * NQT + blockIdx.y) * NBX + blockIdx.x) * (BM * BN);
    const float* p3 = g_part + ((size_t)(3 * NQT + blockIdx.y) * NBX + blockIdx.x) * (BM * BN);

    float bj[4];
#pragma unroll
    for (int j = 0; j < 4; j++) bj[j] = g_binv[bb + tx * 4 + j];

#pragma unroll
    for (int i = 0; i < 4; i++) {
        int row = ty * 4 + i;
        int q = qb + row;
        float qi = g_qinv[q];
        int off = row * BN + tx * 4;
        float4 a = *(const float4*)(p0 + off);
        float4 b = *(const float4*)(p1 + off);
        float4 c = *(const float4*)(p2 + off);
        float4 d = *(const float4*)(p3 + off);
        // fixed summation order: ((s0+s1)+s2)+s3
        float s0 = ((a.x + b.x) + c.x) + d.x;
        float s1 = ((a.y + b.y) + c.y) + d.y;
        float s2 = ((a.z + b.z) + c.z) + d.z;
        float s3 = ((a.w + b.w) + c.w) + d.w;

        float bv[4] = {-3.0e38f, -3.0e38f, -3.0e38f, -3.0e38f};
        int   bi[4] = {0x7fffffff, 0x7fffffff, 0x7fffffff, 0x7fffffff};
        int b0 = bb + tx * 4;
        d_insert(1.0f - s0 * qi * bj[0], b0 + 0, bv, bi);
        d_insert(1.0f - s1 * qi * bj[1], b0 + 1, bv, bi);
        d_insert(1.0f - s2 * qi * bj[2], b0 + 2, bv, bi);
        d_insert(1.0f - s3 * qi * bj[3], b0 + 3, bv, bi);
        shfl_merge_top4<16>(bv, bi);   // across the 16 tx lanes of this row
        if (tx == 0) {
            int base = (q * NBX + blockIdx.x) * 4;
#pragma unroll
            for (int k = 0; k < 4; k++) { g_pv[base + k] = bv[k]; g_pi[base + k] = bi[k]; }
        }
    }
}

// ---------------------------------------------------------------------------
// K3: final top-4 merge. One warp per query folds 32 partials x 4 = 128
// candidates. 32 blocks x 256 threads (8 warps each).
// ---------------------------------------------------------------------------
__global__ void merge_topk_kernel() {
    int tid  = threadIdx.x;
    int lane = tid & 31, wid = tid >> 5;
    int q = blockIdx.x * 8 + wid;

    const float4* pv4 = (const float4*)(g_pv + q * NBX * 4);
    const int4*   pi4 = (const int4*)  (g_pi + q * NBX * 4);
    float4 v = pv4[lane];   // 128 candidates = 1 float4 per lane
    int4   j = pi4[lane];

    float bv[4] = {-3.0e38f, -3.0e38f, -3.0e38f, -3.0e38f};
    int   bi[4] = {0x7fffffff, 0x7fffffff, 0x7fffffff, 0x7fffffff};
    d_insert(v.x, j.x, bv, bi);
    d_insert(v.y, j.y, bv, bi);
    d_insert(v.z, j.z, bv, bi);
    d_insert(v.w, j.w, bv, bi);
    shfl_merge_top4<32>(bv, bi);
    if (lane < 4) g_idx[q * 4 + lane] = bi[lane];
}

// ---------------------------------------------------------------------------
// K4: fused gather. grid=(256, 22), 256 threads.
//   blockIdx.y < 21 : pred_images chunk (HBM-bound bulk, ~83% of spec)
//   blockIdx.y ==21 : grads_m + pred_probs + pred_labels (hidden in the wave)
// ---------------------------------------------------------------------------
__global__ void gather_kernel(const float* __restrict__ img,
                              const float* __restrict__ bank,
                              const float* __restrict__ probs,
                              float* __restrict__ out) {
    int q = blockIdx.x;
    int tid = threadIdx.x;
    __shared__ int ix[4];
    if (tid < 4) ix[tid] = g_idx[q * 4 + tid];
    __syncthreads();

    if (blockIdx.y < 21) {
        const float4* im = (const float4*)img;
        float4* o = (float4*)(out + OFF_IMG) + (size_t)q * IMG4;
        size_t r0 = (size_t)ix[0] * IMG4;
        size_t r1 = (size_t)ix[1] * IMG4;
        size_t r2 = (size_t)ix[2] * IMG4;
        size_t r3 = (size_t)ix[3] * IMG4;
#pragma unroll
        for (int t = 0; t < 7; t++) {
            int f = blockIdx.y * 1792 + t * 256 + tid;   // 21*1792 = 37632 = IMG4
            float4 a = im[r0 + f];
            float4 b = im[r1 + f];
            float4 c = im[r2 + f];
            float4 d = im[r3 + f];
            float4 r;
            r.x = 0.25f * (a.x + b.x + c.x + d.x);
            r.y = 0.25f * (a.y + b.y + c.y + d.y);
            r.z = 0.25f * (a.z + b.z + c.z + d.z);
            r.w = 0.25f * (a.w + b.w + c.w + d.w);
            __stcs(&o[f], r);   // streaming store: no reuse of output
        }
        return;
    }

    // ---- small outputs slice ----
    if (tid < 128) {
        const float4* b0 = (const float4*)(bank + (size_t)ix[0] * DIM);
        const float4* b1 = (const float4*)(bank + (size_t)ix[1] * DIM);
        const float4* b2 = (const float4*)(bank + (size_t)ix[2] * DIM);
        const float4* b3 = (const float4*)(bank + (size_t)ix[3] * DIM);
        float4 a = b0[tid], b = b1[tid], c = b2[tid], d = b3[tid];
        float4 r;
        r.x = 0.25f * (a.x + b.x + c.x + d.x);
        r.y = 0.25f * (a.y + b.y + c.y + d.y);
        r.z = 0.25f * (a.z + b.z + c.z + d.z);
        r.w = 0.25f * (a.w + b.w + c.w + d.w);
        ((float4*)(out + OFF_GRD + (size_t)q * DIM))[tid] = r;
    }

    float bestv = -3.0e38f;
    int   bestc = 0x7fffffff;
    if (tid < 250) {
        const float4* p0 = (const float4*)(probs + (size_t)ix[0] * NC);
        const float4* p1 = (const float4*)(probs + (size_t)ix[1] * NC);
        const float4* p2 = (const float4*)(probs + (size_t)ix[2] * NC);
        const float4* p3 = (const float4*)(probs + (size_t)ix[3] * NC);
        float4 a = p0[tid], b = p1[tid], c = p2[tid], d = p3[tid];
        float4 m;
        m.x = 0.25f * (a.x + b.x + c.x + d.x);
        m.y = 0.25f * (a.y + b.y + c.y + d.y);
        m.z = 0.25f * (a.z + b.z + c.z + d.z);
        m.w = 0.25f * (a.w + b.w + c.w + d.w);
        ((float4*)(out + OFF_PRB + (size_t)q * NC))[tid] = m;
        int c0 = tid * 4;
        bestv = m.x; bestc = c0;
        if (m.y > bestv) { bestv = m.y; bestc = c0 + 1; }
        if (m.z > bestv) { bestv = m.z; bestc = c0 + 2; }
        if (m.w > bestv) { bestv = m.w; bestc = c0 + 3; }
    }
    __shared__ float rv[256];
    __shared__ int   rc[256];
    rv[tid] = bestv; rc[tid] = bestc;
    __syncthreads();
    for (int s = 128; s; s >>= 1) {
        if (tid < s) {
            float v2 = rv[tid + s]; int c2 = rc[tid + s];
            if (v2 > rv[tid] || (v2 == rv[tid] && c2 < rc[tid])) {
                rv[tid] = v2; rc[tid] = c2;
            }
        }
        __syncthreads();
    }
    if (tid == 0) out[OFF_LBL + q] = (float)rc[0];
}

// ---------------------------------------------------------------------------
extern "C" void kernel_launch(void* const* d_in, const int* in_sizes, int n_in,
                              void* d_out, int out_size) {
    const float* feat  = (const float*)d_in[0];
    const float* bank  = (const float*)d_in[1];
    const float* probs = (const float*)d_in[2];
    const float* img   = (const float*)d_in[3];
    float* out = (float*)d_out;

    norms_kernel<<<((N_Q + QB) * 32 + 255) / 256, 256>>>(feat, bank);
    dist_part_kernel<<<dim3(NBX, NQT, SPLITK), 256>>>(feat, bank);
    reduce_topk_kernel<<<dim3(NBX, NQT), 256>>>();
    merge_topk_kernel<<<N_Q / 8, 256>>>();
    gather_kernel<<<dim3(N_Q, 22), 256>>>(img, bank, probs, out);
}

// round 10
// speedup vs baseline: 1.0112x; 1.0032x over previous
#include <cuda_runtime.h>
#include <math.h>

// Problem shapes (fixed by the dataset)
#define N_Q 256      // queries
#define DIM 512      // feature dim
#define QB  2048     // bank size
#define NC  1000     // classes
#define IMG 150528   // 3*224*224
#define IMG4 (IMG/4) // 37632 float4 per image
#define KNN 4

// Output layout (float32, concatenated in reference return order)
#define OFF_LBL 0
#define OFF_PRB 256
#define OFF_IMG 256256           // 256 + 256*1000
#define OFF_GRD 38791424         // OFF_IMG + 256*150528

#define BM 64
#define BN 64
#define BK 32
#define NT (DIM / BK)            // 16 k-tiles
#define NBX (QB / BN)            // 32 partial top-4 blocks per query
#define BMp 65                   // padded smem stride: conflict-free STS

// Scratch (static device globals — no allocations allowed)
__device__ float g_qinv[N_Q];
__device__ float g_binv[QB];
__device__ float g_pv[N_Q * NBX * 4];   // partial top-4 values per (q, col-block)
__device__ int   g_pi[N_Q * NBX * 4];   // partial top-4 indices
__device__ int   g_idx[N_Q * KNN];

// ---------------------------------------------------------------------------
// top-4 helpers: largest-first, ties -> smaller index (lax.top_k order)
// ---------------------------------------------------------------------------
__device__ __forceinline__ bool d_better(float v, int j, float v2, int j2) {
    return (v > v2) || (v == v2 && j < j2);
}
__device__ __forceinline__ void d_insert(float v, int j, float* bv, int* bi) {
    if (!d_better(v, j, bv[3], bi[3])) return;
    int p = 3;
    while (p > 0 && d_better(v, j, bv[p - 1], bi[p - 1])) {
        bv[p] = bv[p - 1]; bi[p] = bi[p - 1]; p--;
    }
    bv[p] = v; bi[p] = j;
}
template<int SPAN>
__device__ __forceinline__ void shfl_merge_top4(float* bv, int* bi) {
#pragma unroll
    for (int o = SPAN / 2; o; o >>= 1) {
        float pv[4]; int pi[4];
#pragma unroll
        for (int k = 0; k < 4; k++) {
            pv[k] = __shfl_xor_sync(0xffffffffu, bv[k], o);
            pi[k] = __shfl_xor_sync(0xffffffffu, bi[k], o);
        }
#pragma unroll
        for (int k = 0; k < 4; k++) d_insert(pv[k], pi[k], bv, bi);
    }
}

// ---------------------------------------------------------------------------
// K0: inverse L2 norms for query rows and bank rows (ONE WARP per row)
// ---------------------------------------------------------------------------
__global__ void norms_kernel(const float* __restrict__ feat,
                             const float* __restrict__ bank) {
    int w    = (blockIdx.x * blockDim.x + threadIdx.x) >> 5;
    int lane = threadIdx.x & 31;
    if (w >= N_Q + QB) return;
    const float* row = (w < N_Q) ? feat + (size_t)w * DIM
                                 : bank + (size_t)(w - N_Q) * DIM;
    const float4* r4 = (const float4*)row;
    float s = 0.f;
#pragma unroll
    for (int i = 0; i < 4; i++) {
        float4 v = r4[lane + 32 * i];
        s += v.x * v.x + v.y * v.y + v.z * v.z + v.w * v.w;
    }
#pragma unroll
    for (int o = 16; o; o >>= 1) s += __shfl_xor_sync(0xffffffffu, s, o);
    if (lane == 0) {
        float inv = 1.0f / fmaxf(sqrtf(s), 1e-12f);
        if (w < N_Q) g_qinv[w] = inv;
        else         g_binv[w - N_Q] = inv;
    }
}

// ---------------------------------------------------------------------------
// K1: distance GEMM + fused per-tile top-4 partials.
// R4's proven 64x64x32 / 256-thread / 4x4-microtile core with three fixes:
//   - smem stride 65: STS of tile is bank-conflict-FREE (was 8-way)
//   - double buffer + register prefetch: one barrier/tile, LDG hidden
//   - fused top-4 epilogue: no 2MB dist matrix, no separate topk kernel
// grid = (QB/64, N_Q/64) = (32, 4) = 128 CTAs.
// ---------------------------------------------------------------------------
__global__ void __launch_bounds__(256)
dist_topk_kernel(const float* __restrict__ A,   // features (N_Q,DIM)
                 const float* __restrict__ B) { // bank     (QB,DIM)
    __shared__ float As[2][BK][BMp];
    __shared__ float Bs[2][BK][BMp];
    int tid = threadIdx.x;
    int tx = tid & 15;        // 0..15 -> 4 bank cols
    int ty = tid >> 4;        // 0..15 -> 4 query rows
    int qb = blockIdx.y * BM;
    int bb = blockIdx.x * BN;
    int r0 = tid >> 3;        // 0..31 (load rows r0 and r0+32)
    int c4 = tid & 7;         // 0..7  (float4 col in k-slab)

    const float4* Ag0 = (const float4*)(A + (size_t)(qb + r0)      * DIM) + c4;
    const float4* Ag1 = (const float4*)(A + (size_t)(qb + r0 + 32) * DIM) + c4;
    const float4* Bg0 = (const float4*)(B + (size_t)(bb + r0)      * DIM) + c4;
    const float4* Bg1 = (const float4*)(B + (size_t)(bb + r0 + 32) * DIM) + c4;

    float acc[4][4] = {};

    float4 va0 = Ag0[0], va1 = Ag1[0], vb0 = Bg0[0], vb1 = Bg1[0];
    // store tile 0 -> buffer 0 (transposed; stride 65 -> conflict-free)
    {
        As[0][c4 * 4 + 0][r0] = va0.x; As[0][c4 * 4 + 1][r0] = va0.y;
        As[0][c4 * 4 + 2][r0] = va0.z; As[0][c4 * 4 + 3][r0] = va0.w;
        As[0][c4 * 4 + 0][r0 + 32] = va1.x; As[0][c4 * 4 + 1][r0 + 32] = va1.y;
        As[0][c4 * 4 + 2][r0 + 32] = va1.z; As[0][c4 * 4 + 3][r0 + 32] = va1.w;
        Bs[0][c4 * 4 + 0][r0] = vb0.x; Bs[0][c4 * 4 + 1][r0] = vb0.y;
        Bs[0][c4 * 4 + 2][r0] = vb0.z; Bs[0][c4 * 4 + 3][r0] = vb0.w;
        Bs[0][c4 * 4 + 0][r0 + 32] = vb1.x; Bs[0][c4 * 4 + 1][r0 + 32] = vb1.y;
        Bs[0][c4 * 4 + 2][r0 + 32] = vb1.z; Bs[0][c4 * 4 + 3][r0 + 32] = vb1.w;
    }
    __syncthreads();

    for (int t = 0; t < NT; t++) {
        if (t + 1 < NT) {                 // prefetch next tile into registers
            va0 = Ag0[(t + 1) * (BK / 4)]; va1 = Ag1[(t + 1) * (BK / 4)];
            vb0 = Bg0[(t + 1) * (BK / 4)]; vb1 = Bg1[(t + 1) * (BK / 4)];
        }
        int cur = t & 1;
#pragma unroll
        for (int k = 0; k < BK; k++) {
            float ra[4], rb[4];
#pragma unroll
            for (int i = 0; i < 4; i++) ra[i] = As[cur][k][ty * 4 + i];
#pragma unroll
            for (int j = 0; j < 4; j++) rb[j] = Bs[cur][k][tx * 4 + j];
#pragma unroll
            for (int i = 0; i < 4; i++)
#pragma unroll
                for (int j = 0; j < 4; j++)
                    acc[i][j] = fmaf(ra[i], rb[j], acc[i][j]);
        }
        if (t + 1 < NT) {                 // store prefetch -> other buffer
            int nb = (t + 1) & 1;
            As[nb][c4 * 4 + 0][r0] = va0.x; As[nb][c4 * 4 + 1][r0] = va0.y;
            As[nb][c4 * 4 + 2][r0] = va0.z; As[nb][c4 * 4 + 3][r0] = va0.w;
            As[nb][c4 * 4 + 0][r0 + 32] = va1.x; As[nb][c4 * 4 + 1][r0 + 32] = va1.y;
            As[nb][c4 * 4 + 2][r0 + 32] = va1.z; As[nb][c4 * 4 + 3][r0 + 32] = va1.w;
            Bs[nb][c4 * 4 + 0][r0] = vb0.x; Bs[nb][c4 * 4 + 1][r0] = vb0.y;
            Bs[nb][c4 * 4 + 2][r0] = vb0.z; Bs[nb][c4 * 4 + 3][r0] = vb0.w;
            Bs[nb][c4 * 4 + 0][r0 + 32] = vb1.x; Bs[nb][c4 * 4 + 1][r0 + 32] = vb1.y;
            Bs[nb][c4 * 4 + 2][r0 + 32] = vb1.z; Bs[nb][c4 * 4 + 3][r0 + 32] = vb1.w;
        }
        __syncthreads();
    }

    // Epilogue: distances + per-row top-4 over this CTA's 64 columns.
    float bj[4];
#pragma unroll
    for (int j = 0; j < 4; j++) bj[j] = g_binv[bb + tx * 4 + j];

#pragma unroll
    for (int i = 0; i < 4; i++) {
        int q = qb + ty * 4 + i;
        float qi = g_qinv[q];
        float bv[4] = {-3.0e38f, -3.0e38f, -3.0e38f, -3.0e38f};
        int   bi[4] = {0x7fffffff, 0x7fffffff, 0x7fffffff, 0x7fffffff};
        int b0 = bb + tx * 4;
#pragma unroll
        for (int j = 0; j < 4; j++)
            d_insert(1.0f - acc[i][j] * qi * bj[j], b0 + j, bv, bi);
        shfl_merge_top4<16>(bv, bi);   // across the 16 tx lanes of this row
        if (tx == 0) {
            int base = (q * NBX + blockIdx.x) * 4;
#pragma unroll
            for (int k = 0; k < 4; k++) { g_pv[base + k] = bv[k]; g_pi[base + k] = bi[k]; }
        }
    }
}

// ---------------------------------------------------------------------------
// K2: final top-4 merge. One warp per query folds 32 partials x 4 = 128
// candidates. 32 blocks x 256 threads (8 warps each).
// ---------------------------------------------------------------------------
__global__ void merge_topk_kernel() {
    int tid  = threadIdx.x;
    int lane = tid & 31, wid = tid >> 5;
    int q = blockIdx.x * 8 + wid;

    const float4* pv4 = (const float4*)(g_pv + q * NBX * 4);
    const int4*   pi4 = (const int4*)  (g_pi + q * NBX * 4);
    float4 v = pv4[lane];   // 128 candidates = 1 float4 per lane
    int4   j = pi4[lane];

    float bv[4] = {-3.0e38f, -3.0e38f, -3.0e38f, -3.0e38f};
    int   bi[4] = {0x7fffffff, 0x7fffffff, 0x7fffffff, 0x7fffffff};
    d_insert(v.x, j.x, bv, bi);
    d_insert(v.y, j.y, bv, bi);
    d_insert(v.z, j.z, bv, bi);
    d_insert(v.w, j.w, bv, bi);
    shfl_merge_top4<32>(bv, bi);
    if (lane < 4) g_idx[q * 4 + lane] = bi[lane];
}

// ---------------------------------------------------------------------------
// K3: fused gather. grid=(256, 22), 256 threads.
//   blockIdx.y < 21 : pred_images chunk (HBM-bound bulk, ~83% of spec)
//   blockIdx.y ==21 : grads_m + pred_probs + pred_labels (hidden in the wave)
// ---------------------------------------------------------------------------
__global__ void gather_kernel(const float* __restrict__ img,
                              const float* __restrict__ bank,
                              const float* __restrict__ probs,
                              float* __restrict__ out) {
    int q = blockIdx.x;
    int tid = threadIdx.x;
    __shared__ int ix[4];
    if (tid < 4) ix[tid] = g_idx[q * 4 + tid];
    __syncthreads();

    if (blockIdx.y < 21) {
        const float4* im = (const float4*)img;
        float4* o = (float4*)(out + OFF_IMG) + (size_t)q * IMG4;
        size_t r0 = (size_t)ix[0] * IMG4;
        size_t r1 = (size_t)ix[1] * IMG4;
        size_t r2 = (size_t)ix[2] * IMG4;
        size_t r3 = (size_t)ix[3] * IMG4;
#pragma unroll
        for (int t = 0; t < 7; t++) {
            int f = blockIdx.y * 1792 + t * 256 + tid;   // 21*1792 = 37632 = IMG4
            float4 a = im[r0 + f];
            float4 b = im[r1 + f];
            float4 c = im[r2 + f];
            float4 d = im[r3 + f];
            float4 r;
            r.x = 0.25f * (a.x + b.x + c.x + d.x);
            r.y = 0.25f * (a.y + b.y + c.y + d.y);
            r.z = 0.25f * (a.z + b.z + c.z + d.z);
            r.w = 0.25f * (a.w + b.w + c.w + d.w);
            __stcs(&o[f], r);   // streaming store: no reuse of output
        }
        return;
    }

    // ---- small outputs slice ----
    if (tid < 128) {
        const float4* b0 = (const float4*)(bank + (size_t)ix[0] * DIM);
        const float4* b1 = (const float4*)(bank + (size_t)ix[1] * DIM);
        const float4* b2 = (const float4*)(bank + (size_t)ix[2] * DIM);
        const float4* b3 = (const float4*)(bank + (size_t)ix[3] * DIM);
        float4 a = b0[tid], b = b1[tid], c = b2[tid], d = b3[tid];
        float4 r;
        r.x = 0.25f * (a.x + b.x + c.x + d.x);
        r.y = 0.25f * (a.y + b.y + c.y + d.y);
        r.z = 0.25f * (a.z + b.z + c.z + d.z);
        r.w = 0.25f * (a.w + b.w + c.w + d.w);
        ((float4*)(out + OFF_GRD + (size_t)q * DIM))[tid] = r;
    }

    float bestv = -3.0e38f;
    int   bestc = 0x7fffffff;
    if (tid < 250) {
        const float4* p0 = (const float4*)(probs + (size_t)ix[0] * NC);
        const float4* p1 = (const float4*)(probs + (size_t)ix[1] * NC);
        const float4* p2 = (const float4*)(probs + (size_t)ix[2] * NC);
        const float4* p3 = (const float4*)(probs + (size_t)ix[3] * NC);
        float4 a = p0[tid], b = p1[tid], c = p2[tid], d = p3[tid];
        float4 m;
        m.x = 0.25f * (a.x + b.x + c.x + d.x);
        m.y = 0.25f * (a.y + b.y + c.y + d.y);
        m.z = 0.25f * (a.z + b.z + c.z + d.z);
        m.w = 0.25f * (a.w + b.w + c.w + d.w);
        ((float4*)(out + OFF_PRB + (size_t)q * NC))[tid] = m;
        int c0 = tid * 4;
        bestv = m.x; bestc = c0;
        if (m.y > bestv) { bestv = m.y; bestc = c0 + 1; }
        if (m.z > bestv) { bestv = m.z; bestc = c0 + 2; }
        if (m.w > bestv) { bestv = m.w; bestc = c0 + 3; }
    }
    __shared__ float rv[256];
    __shared__ int   rc[256];
    rv[tid] = bestv; rc[tid] = bestc;
    __syncthreads();
    for (int s = 128; s; s >>= 1) {
        if (tid < s) {
            float v2 = rv[tid + s]; int c2 = rc[tid + s];
            if (v2 > rv[tid] || (v2 == rv[tid] && c2 < rc[tid])) {
                rv[tid] = v2; rc[tid] = c2;
            }
        }
        __syncthreads();
    }
    if (tid == 0) out[OFF_LBL + q] = (float)rc[0];
}

// ---------------------------------------------------------------------------
extern "C" void kernel_launch(void* const* d_in, const int* in_sizes, int n_in,
                              void* d_out, int out_size) {
    const float* feat  = (const float*)d_in[0];
    const float* bank  = (const float*)d_in[1];
    const float* probs = (const float*)d_in[2];
    const float* img   = (const float*)d_in[3];
    float* out = (float*)d_out;

    norms_kernel<<<((N_Q + QB) * 32 + 255) / 256, 256>>>(feat, bank);
    dist_topk_kernel<<<dim3(QB / BN, N_Q / BM), 256>>>(feat, bank);
    merge_topk_kernel<<<N_Q / 8, 256>>>();
    gather_kernel<<<dim3(N_Q, 22), 256>>>(img, bank, probs, out);
}